// round 9
// baseline (speedup 1.0000x reference)
#include <cuda_runtime.h>
#include <cuda_fp16.h>
#include <cstdint>

#define NVEC    131072
#define DDIM    128
#define KCODES  1024
#define BN      64               // vectors per CTA
#define BKC     256              // codes per chunk
#define NCHUNK  (KCODES / BKC)
#define NTHREADS 256
#define CSCALE  8192.f           // exact pow2 codebook prescale (fp16 range lift)

// dynamic smem (bytes)
#define SMO_ZS  0                           // half2[64][64]   z tile (dw-major)
#define SMO_CS  16384                       // half2[64][256]  code chunk
#define SMO_SS  81920                       // float[1024]     snorm
#define SMO_MM  86016                       // float[64]       per-vector margin
#define SMEM_TOTAL 86272

typedef unsigned long long u64;

__device__ __half2       g_cw[64 * KCODES];  // scaled fp16 codebook, [dw][k]
__device__ float         g_snorm[KCODES];    // exact sequential ||c||^2
__device__ int           g_camax_bits = 0;   // max |c| (float bits, idempotent)
__device__ unsigned char g_ccnt[32][NVEC];
__device__ int           g_cand[32][NVEC][2];
__device__ int           g_idx[NVEC];

// Prologue: exact sequential fp32 ||c||^2 + amax + scaled fp16 transpose.
__global__ void cbprep_kernel(const float* __restrict__ cb) {
    int k = blockIdx.x * blockDim.x + threadIdx.x;
    if (k >= KCODES) return;
    const float4* row = (const float4*)(cb + k * DDIM);
    float s = 0.f, amax = 0.f;
#pragma unroll
    for (int w = 0; w < 32; w++) {
        float4 v = row[w];
        s = __fadd_rn(s, __fmul_rn(v.x, v.x));
        s = __fadd_rn(s, __fmul_rn(v.y, v.y));
        s = __fadd_rn(s, __fmul_rn(v.z, v.z));
        s = __fadd_rn(s, __fmul_rn(v.w, v.w));
        amax = fmaxf(amax, fmaxf(fmaxf(fabsf(v.x), fabsf(v.y)),
                                 fmaxf(fabsf(v.z), fabsf(v.w))));
        g_cw[(2 * w) * KCODES + k]     = __floats2half2_rn(v.x * CSCALE, v.y * CSCALE);
        g_cw[(2 * w + 1) * KCODES + k] = __floats2half2_rn(v.z * CSCALE, v.w * CSCALE);
    }
    g_snorm[k] = s;
    atomicMax(&g_camax_bits, __float_as_int(amax));
}

// Filter: fp16 HFMA2 GEMM (2 MAC/lane/issue) + rigorous-margin capture.
__global__ void __launch_bounds__(NTHREADS, 2)
filter_kernel(const float* __restrict__ z) {
    extern __shared__ char smem[];
    __half2* zs = (__half2*)(smem + SMO_ZS);
    __half2* cs = (__half2*)(smem + SMO_CS);
    float*   ss = (float*)(smem + SMO_SS);
    float*   mm = (float*)(smem + SMO_MM);

    const int tid = threadIdx.x, tn = tid >> 5, tk = tid & 31;
    const int nbase = blockIdx.x * BN;
    const float* zb = z + (size_t)(nbase >> 12) * (DDIM * 4096) + (nbase & 4095);

    for (int i = tid; i < KCODES; i += NTHREADS) ss[i] = g_snorm[i];

    // z tile: gmem [d][v] coalesced -> smem half2 (d=2dw, 2dw+1 packed).
    for (int t = tid; t < 64 * BN; t += NTHREADS) {
        int dw = t >> 6, v = t & 63;
        zs[t] = __floats2half2_rn(zb[(size_t)(2 * dw) * 4096 + v],
                                  zb[(size_t)(2 * dw + 1) * 4096 + v]);
    }
    __syncthreads();

    // Per-vector rigorous margin: M = 2*kappa*E + tie/fp32 slack,
    // E = amax_c * L1(z_hat), kappa = 66.5*2^-11 (conservative 0.0335).
    if (tid < BN) {
        float l1 = 0.f;
#pragma unroll 8
        for (int dw = 0; dw < 64; dw++) {
            __half2 h = zs[dw * BN + tid];
            l1 += fabsf(__low2float(h)) + fabsf(__high2float(h));
        }
        float E = __int_as_float(g_camax_bits) * l1 * 1.002f;
        mm[tid] = 2.f * 0.0335f * E + 1.2e-4f;
    }

    float tM[8], rm[8];
    int cnt[8], c0r[8], c1r[8];
#pragma unroll
    for (int i = 0; i < 8; i++) { rm[i] = 3.4e38f; cnt[i] = 0; c0r[i] = 0; c1r[i] = 0; }

    for (int ch = 0; ch < NCHUNK; ch++) {
        __syncthreads();
        // code chunk: g_cw [dw][k] -> cs [dw][256], both k-contiguous (coalesced).
        const __half2* src = g_cw + ch * BKC;
        for (int t = tid; t < 64 * BKC; t += NTHREADS)
            cs[t] = src[(t >> 8) * KCODES + (t & 255)];
        __syncthreads();
        if (ch == 0) {
#pragma unroll
            for (int i = 0; i < 8; i++) tM[i] = mm[tn * 8 + i];
        }

        __half2 acc[64];
#pragma unroll
        for (int a = 0; a < 64; a++) acc[a] = __floats2half2_rn(0.f, 0.f);

#pragma unroll 4
        for (int dw = 0; dw < 64; dw++) {
            __half2 zv[8], cv[8];
            const __half2* zp = zs + dw * BN + tn * 8;
            const __half2* cp = cs + dw * BKC + tk * 8;
            *(uint4*)&zv[0] = *(const uint4*)zp;
            *(uint4*)&zv[4] = *(const uint4*)(zp + 4);
            *(uint4*)&cv[0] = *(const uint4*)cp;
            *(uint4*)&cv[4] = *(const uint4*)(cp + 4);
#pragma unroll
            for (int i = 0; i < 8; i++)
#pragma unroll
                for (int j = 0; j < 8; j++)
                    acc[i * 8 + j] = __hfma2(zv[i], cv[j], acc[i * 8 + j]);
        }

        // Epilogue per vector: d_hat = s_k - 2*p (||z||^2 cancels in argmin).
        const int kb = ch * BKC + tk * 8;
        float sj[8];
        *(float4*)&sj[0] = *(const float4*)(ss + kb);
        *(float4*)&sj[4] = *(const float4*)(ss + kb + 4);
#pragma unroll
        for (int i = 0; i < 8; i++) {
            float dv[8];
            float mn = 3.4e38f;
#pragma unroll
            for (int j = 0; j < 8; j++) {
                __half2 a = acc[i * 8 + j];
                float p = (__low2float(a) + __high2float(a)) * (1.f / CSCALE);
                dv[j] = __fmaf_rn(-2.f, p, sj[j]);
                mn = fminf(mn, dv[j]);
            }
#pragma unroll
            for (int off = 16; off > 0; off >>= 1)
                mn = fminf(mn, __shfl_xor_sync(~0u, mn, off));
            rm[i] = fminf(rm[i], mn);
            const float t = rm[i] + tM[i];
#pragma unroll
            for (int j = 0; j < 8; j++) {
                if (dv[j] <= t) {
                    if (cnt[i] == 0) c0r[i] = kb + j;
                    else if (cnt[i] == 1) c1r[i] = kb + j;
                    cnt[i]++;
                }
            }
        }
    }

    const int n0 = nbase + tn * 8;
    u64 pk = 0;
#pragma unroll
    for (int i = 0; i < 8; i++) pk |= (u64)(cnt[i] > 3 ? 3 : cnt[i]) << (8 * i);
    *(u64*)&g_ccnt[tk][n0] = pk;
#pragma unroll
    for (int i = 0; i < 8; i++) {
        if (cnt[i] > 0) g_cand[tk][n0 + i][0] = c0r[i];
        if (cnt[i] > 1) g_cand[tk][n0 + i][1] = c1r[i];
    }
}

// Exact rescue: bit-identical reference arithmetic on candidates.
__global__ void rescue_kernel(const float* __restrict__ z,
                              const float* __restrict__ cb) {
    int n = blockIdx.x * blockDim.x + threadIdx.x;
    int total = 0, lastlane = 0;
    bool full = false;
#pragma unroll
    for (int lane = 0; lane < 32; lane++) {
        int c = g_ccnt[lane][n];
        if (c > 2) full = true;
        if (c > 0) { total += c; lastlane = lane; }
    }
    if (!full && total == 1) { g_idx[n] = g_cand[lastlane][n][0]; return; }

    float zr[DDIM];
    const float* zp = z + (size_t)(n >> 12) * (DDIM * 4096) + (n & 4095);
#pragma unroll
    for (int d = 0; d < DDIM; d++) zr[d] = zp[(size_t)d * 4096];

    float rr = 0.f;
#pragma unroll
    for (int d = 0; d < DDIM; d++)
        rr = __fadd_rn(rr, __fmul_rn(zr[d], zr[d]));

    float bd = 3.4e38f;
    int bk = 0x7fffffff;
    if (full) {
        for (int k = 0; k < KCODES; k++) {
            const float* crow = cb + k * DDIM;
            float p = 0.f;
#pragma unroll
            for (int d = 0; d < DDIM; d++) p = __fmaf_rn(zr[d], crow[d], p);
            float dist = __fmaf_rn(-2.f, p, __fadd_rn(rr, g_snorm[k]));
            if (dist < bd || (dist == bd && k < bk)) { bd = dist; bk = k; }
        }
    } else {
#pragma unroll 1
        for (int lane = 0; lane < 32; lane++) {
            int c = g_ccnt[lane][n];
#pragma unroll 1
            for (int i = 0; i < c; i++) {
                int k = g_cand[lane][n][i];
                const float* crow = cb + k * DDIM;
                float p = 0.f;
#pragma unroll
                for (int d = 0; d < DDIM; d++) p = __fmaf_rn(zr[d], crow[d], p);
                float dist = __fmaf_rn(-2.f, p, __fadd_rn(rr, g_snorm[k]));
                if (dist < bd || (dist == bd && k < bk)) { bd = dist; bk = k; }
            }
        }
    }
    g_idx[n] = bk;
}

// Gather: float4 codebook reads, fully-coalesced writes.
__global__ void gather_kernel(const float* __restrict__ cb, float* __restrict__ out) {
    int t = blockIdx.x * blockDim.x + threadIdx.x;   // t < NVEC*32
    int hw = t & 4095;
    int i4 = (t >> 12) & 31;
    int b  = t >> 17;
    int n  = (b << 12) | hw;
    float4 v = *(const float4*)(cb + g_idx[n] * DDIM + i4 * 4);
    size_t o = ((size_t)b << 19) | ((size_t)(i4 * 4) << 12) | (size_t)hw;
    out[o]         = v.x;
    out[o + 4096]  = v.y;
    out[o + 8192]  = v.z;
    out[o + 12288] = v.w;
}

extern "C" void kernel_launch(void* const* d_in, const int* in_sizes, int n_in,
                              void* d_out, int out_size) {
    const float* z  = (const float*)d_in[0];
    const float* cb = (const float*)d_in[1];
    float* out = (float*)d_out;

    cudaFuncSetAttribute(filter_kernel,
                         cudaFuncAttributeMaxDynamicSharedMemorySize, SMEM_TOTAL);

    cbprep_kernel<<<(KCODES + 255) / 256, 256>>>(cb);
    filter_kernel<<<NVEC / BN, NTHREADS, SMEM_TOTAL>>>(z);
    rescue_kernel<<<NVEC / 256, 256>>>(z, cb);
    gather_kernel<<<(NVEC * 32) / 256, 256>>>(cb, out);
}

// round 10
// speedup vs baseline: 6.6095x; 6.6095x over previous
#include <cuda_runtime.h>
#include <cstdint>

#define NVEC     131072      // 32 * 64 * 64 vectors
#define DDIM     128
#define KCODES   1024
#define BN       64          // vectors per block
#define BKC      128         // codes per chunk
#define CSTR     129         // padded row stride for code tile (conflict-free)
#define NTHREADS 256

#define SMEM_BYTES ((DDIM * BN + DDIM * CSTR + BN) * 4)   // 99072 B -> 2 CTAs/SM

typedef unsigned long long u64;

__device__ int   g_idx[NVEC];
__device__ float g_snorm[KCODES];

// ||c_k||^2: float4 loads (width only), strictly sequential i=0..127 fp32
// mul+add — bit-identical to the reference's elementwise square -> sum.
__global__ void snorm_kernel(const float* __restrict__ cb) {
    int k = blockIdx.x * blockDim.x + threadIdx.x;
    if (k >= KCODES) return;
    const float4* row = (const float4*)(cb + k * DDIM);
    float s = 0.f;
#pragma unroll
    for (int i = 0; i < 32; i++) {
        float4 v = row[i];
        s = __fadd_rn(s, __fmul_rn(v.x, v.x));
        s = __fadd_rn(s, __fmul_rn(v.y, v.y));
        s = __fadd_rn(s, __fmul_rn(v.z, v.z));
        s = __fadd_rn(s, __fmul_rn(v.w, v.w));
    }
    g_snorm[k] = s;
}

// For each of BN vectors: argmin_k fl( fl(r + s_k) - 2*p_k ), lowest-index
// tie-break, replicating the reference's fp32 quantized comparison exactly.
__global__ void __launch_bounds__(NTHREADS, 2)
argmin_kernel(const float* __restrict__ z, const float* __restrict__ cb) {
    extern __shared__ float smem[];
    float* zs = smem;                 // [128][64]   z tile, transposed (d-major)
    float* cs = smem + DDIM * BN;     // [128][129]  code tile, padded
    float* rs = cs + DDIM * CSTR;     // [64]        ||z||^2 per vector

    const int nbase = blockIdx.x * BN;
    const int b  = nbase >> 12;          // n = b*4096 + h*64 + w
    const int hw = nbase & 4095;
    const float* zb = z + (size_t)b * (DDIM * 4096) + hw;

    // Load z tile: global coalesced over hw, smem write conflict-free.
    for (int t = threadIdx.x; t < DDIM * BN; t += NTHREADS) {
        int i = t >> 6, nl = t & (BN - 1);
        zs[i * BN + nl] = zb[(size_t)i * 4096 + nl];
    }
    __syncthreads();

    // r_n = sequential fp32 sum of squares over d (i = 0..127 in order).
    // Unrolled: loads pipeline; the FADD chain is a serial dependency so its
    // order (and hence the result bits) is unchanged.
    if (threadIdx.x < BN) {
        float r = 0.f;
#pragma unroll
        for (int i = 0; i < DDIM; i++) {
            float v = zs[i * BN + threadIdx.x];
            r = __fadd_rn(r, __fmul_rn(v, v));
        }
        rs[threadIdx.x] = r;
    }
    __syncthreads();

    const int tn = threadIdx.x >> 5;   // warp id: owns vectors tn*8..tn*8+7
    const int tk = threadIdx.x & 31;   // lane: owns codes tk + 32*j, j<4

    float rreg[8];
#pragma unroll
    for (int n = 0; n < 8; n++) rreg[n] = rs[tn * 8 + n];

    float best[8];
    int   bidx[8];
#pragma unroll
    for (int n = 0; n < 8; n++) { best[n] = 3.4e38f; bidx[n] = 0; }

    for (int chunk = 0; chunk < KCODES / BKC; chunk++) {
        const int kbase = chunk * BKC;
        __syncthreads();
        // Fill code tile transposed: gmem coalesced over i, stride-129 writes
        // (bank = (i + kl) mod 32 within a warp -> conflict-free).
        for (int t = threadIdx.x; t < BKC * DDIM; t += NTHREADS) {
            int kl = t >> 7, i = t & (DDIM - 1);
            cs[i * CSTR + kl] = cb[(kbase + kl) * DDIM + i];
        }
        __syncthreads();

        // accp[n2*4+j]: lo = acc[2*n2][j], hi = acc[2*n2+1][j]
        u64 accp[16];
#pragma unroll
        for (int a = 0; a < 16; a++) accp[a] = 0ull;

#pragma unroll 4
        for (int d = 0; d < DDIM; d++) {
            const float* zrow = zs + d * BN + tn * 8;
            u64 zp[4];
#pragma unroll
            for (int n2 = 0; n2 < 4; n2++)
                zp[n2] = *(const u64*)(zrow + 2 * n2);   // (z[2n2], z[2n2+1])
            const float* crow = cs + d * CSTR + tk;
#pragma unroll
            for (int j = 0; j < 4; j++) {
                float c = crow[j * 32];
                u64 cd;
                asm("mov.b64 %0, {%1, %1};" : "=l"(cd) : "f"(c));
#pragma unroll
                for (int n2 = 0; n2 < 4; n2++)
                    asm("fma.rn.f32x2 %0, %1, %2, %0;"
                        : "+l"(accp[n2 * 4 + j]) : "l"(zp[n2]), "l"(cd));
            }
        }

        // dist = fl( fl(r + s_k) - 2*p ): 2*p exact in fp32, so the fused
        // FMA's single rounding equals the reference's separate subtract.
        // Compare order: k ascending per lane (chunk asc, j asc) — identical
        // tie resolution to the proven round-2 kernel.
#pragma unroll
        for (int j = 0; j < 4; j++) {
            const int k = kbase + tk + j * 32;
            const float s = g_snorm[k];
#pragma unroll
            for (int n2 = 0; n2 < 4; n2++) {
                u64 ap = accp[n2 * 4 + j];
                float plo = __uint_as_float((unsigned)(ap & 0xffffffffu));
                float phi = __uint_as_float((unsigned)(ap >> 32));
                int nlo = 2 * n2, nhi = 2 * n2 + 1;
                float dlo = __fmaf_rn(-2.f, plo, __fadd_rn(rreg[nlo], s));
                float dhi = __fmaf_rn(-2.f, phi, __fadd_rn(rreg[nhi], s));
                if (dlo < best[nlo] || (dlo == best[nlo] && k < bidx[nlo])) {
                    best[nlo] = dlo; bidx[nlo] = k;
                }
                if (dhi < best[nhi] || (dhi == best[nhi] && k < bidx[nhi])) {
                    best[nhi] = dhi; bidx[nhi] = k;
                }
            }
        }
    }

    // Cross-lane argmin per vector, lowest-index tie-break.
#pragma unroll
    for (int n = 0; n < 8; n++) {
        float v = best[n]; int id = bidx[n];
#pragma unroll
        for (int off = 16; off > 0; off >>= 1) {
            float v2 = __shfl_down_sync(0xffffffffu, v, off);
            int   i2 = __shfl_down_sync(0xffffffffu, id, off);
            if (v2 < v || (v2 == v && i2 < id)) { v = v2; id = i2; }
        }
        if (tk == 0) g_idx[nbase + tn * 8 + n] = id;
    }
}

// Gather: float4 codebook reads, fully-coalesced writes (measured 24us).
__global__ void gather_kernel(const float* __restrict__ cb, float* __restrict__ out) {
    int t = blockIdx.x * blockDim.x + threadIdx.x;   // t < NVEC*32
    int hw = t & 4095;
    int i4 = (t >> 12) & 31;
    int b  = t >> 17;
    int n  = (b << 12) | hw;
    float4 v = *(const float4*)(cb + g_idx[n] * DDIM + i4 * 4);
    size_t o = ((size_t)b << 19) | ((size_t)(i4 * 4) << 12) | (size_t)hw;
    out[o]         = v.x;
    out[o + 4096]  = v.y;
    out[o + 8192]  = v.z;
    out[o + 12288] = v.w;
}

extern "C" void kernel_launch(void* const* d_in, const int* in_sizes, int n_in,
                              void* d_out, int out_size) {
    const float* z  = (const float*)d_in[0];
    const float* cb = (const float*)d_in[1];
    float* out = (float*)d_out;

    cudaFuncSetAttribute(argmin_kernel,
                         cudaFuncAttributeMaxDynamicSharedMemorySize, SMEM_BYTES);

    snorm_kernel<<<(KCODES + 255) / 256, 256>>>(cb);
    argmin_kernel<<<NVEC / BN, NTHREADS, SMEM_BYTES>>>(z, cb);
    gather_kernel<<<(NVEC * 32) / 256, 256>>>(cb, out);
}